// round 16
// baseline (speedup 1.0000x reference)
#include <cuda_runtime.h>
#include <cuda_fp16.h>
#include <math.h>
#include <stdint.h>

// ---------------------------------------------------------------------------
// Problem constants
// ---------------------------------------------------------------------------
#define BB 4
#define SS 4096
#define DD 1024
#define HH 16
#define FF 256
#define HD 64
#define NN (BB * SS)          // 16384 rows
#define GK 1024               // GEMM K

// ---------------------------------------------------------------------------
// Scratch (device globals; no allocations allowed). Pure fp16 operands;
// only kv/ksum accumulate in fp32 (atomics), ksum re-split into kvx cols 64/65.
// ---------------------------------------------------------------------------
__device__ __half g_xh[NN * DD];
__device__ __half g_wh[4 * DD * DD];
__device__ __half g_rfh[HH * HD * FF];

__device__ __half g_qh[NN * DD];
__device__ __half g_kh[NN * DD];
__device__ __half g_vh[NN * DD];
__device__ __half g_yh[NN * DD];

__device__ __half g_qph[(size_t)BB * HH * SS * FF];
__device__ __half g_kph[(size_t)BB * HH * SS * FF];

__device__ float g_kv[(size_t)BB * HH * FF * HD];     // fp32 (atomics)
__device__ float g_ksum[(size_t)BB * HH * FF];
// extended kv: 72 cols = kv(64) | ksum_hi(64) ksum_lo(65) | zeros(66-71)
__device__ __half g_kvh[(size_t)BB * HH * FF * 72];

// ---------------------------------------------------------------------------
// PTX helpers (base-target: cp.async / ldmatrix / mma.sync)
// ---------------------------------------------------------------------------
__device__ __forceinline__ uint32_t smem_u32(const void* p) {
    return (uint32_t)__cvta_generic_to_shared(p);
}
__device__ __forceinline__ void cp_async16(uint32_t dst, const void* src) {
    asm volatile("cp.async.cg.shared.global [%0], [%1], 16;"
                 :: "r"(dst), "l"(src) : "memory");
}
__device__ __forceinline__ void ldm_x4(uint32_t& r0, uint32_t& r1,
                                       uint32_t& r2, uint32_t& r3, uint32_t addr) {
    asm volatile("ldmatrix.sync.aligned.m8n8.x4.shared.b16 {%0,%1,%2,%3}, [%4];"
                 : "=r"(r0), "=r"(r1), "=r"(r2), "=r"(r3) : "r"(addr));
}
__device__ __forceinline__ void ldm_x4_t(uint32_t& r0, uint32_t& r1,
                                         uint32_t& r2, uint32_t& r3, uint32_t addr) {
    asm volatile("ldmatrix.sync.aligned.m8n8.x4.trans.shared.b16 {%0,%1,%2,%3}, [%4];"
                 : "=r"(r0), "=r"(r1), "=r"(r2), "=r"(r3) : "r"(addr));
}
__device__ __forceinline__ void mma16816(float* c, uint32_t a0, uint32_t a1,
                                         uint32_t a2, uint32_t a3,
                                         uint32_t b0, uint32_t b1) {
    asm volatile(
        "mma.sync.aligned.m16n8k16.row.col.f32.f16.f16.f32 "
        "{%0,%1,%2,%3}, {%4,%5,%6,%7}, {%8,%9}, {%0,%1,%2,%3};"
        : "+f"(c[0]), "+f"(c[1]), "+f"(c[2]), "+f"(c[3])
        : "r"(a0), "r"(a1), "r"(a2), "r"(a3), "r"(b0), "r"(b1));
}
__device__ __forceinline__ uint32_t taddr(uint32_t base, int stride,
                                          int k0, int col0, int lane) {
    int g = lane >> 3, r = lane & 7;
    return base + (uint32_t)((k0 + ((g >> 1) << 3) + r) * stride
                             + (col0 + ((g & 1) << 3)) * 2);
}
__device__ __forceinline__ void split2(float v, __half& h, __half& l) {
    h = __float2half_rn(v);
    l = __float2half_rn(v - __half2float(h));
}
__device__ __forceinline__ float softplusf(float x) {
    return fmaxf(x, 0.0f) + log1pf(expf(-fabsf(x)));
}

// ---------------------------------------------------------------------------
// HMMA single-pass fp16 GEMM-NT: C = A @ B^T + bias.
// 128x128x64 CTA tile, 2 smem tiles per stage (A, B), 3 stages
// -> 110.6 KB smem -> 2 CTAs/SM. Single barrier per chunk, issue-before-compute.
// ---------------------------------------------------------------------------
#define KC 64
#define ROWB 144                         // 128B data + 16B pad; 9 mod 8 = 1
#define TILE_B (128 * ROWB)              // 18432
#define STAGE_B (2 * TILE_B)             // 36864 (A, B)
#define NSTAGE 3
#define GEMM_DSMEM (NSTAGE * STAGE_B)    // 110592 B

template <int HALF_OUT>
__device__ __forceinline__ void gemm_core(
    const __half* __restrict__ A, const __half* __restrict__ B,
    const float* __restrict__ bias, float* __restrict__ C,
    __half* __restrict__ Ch, int Mcols) {
    extern __shared__ char dsm[];
    const uint32_t sbase = smem_u32(dsm);

    const int tid = threadIdx.x;
    const int wid = tid >> 5, lane = tid & 31;
    const int warp_m = wid >> 2;
    const int warp_n = wid & 3;
    const int bm = blockIdx.x * 128;
    const int bn = blockIdx.y * 128;

    const int lrow = lane & 15;
    const int lchunk = (lane >> 4) * 16;

    float acc[4][4][4];
#pragma unroll
    for (int i = 0; i < 4; ++i)
#pragma unroll
        for (int j = 0; j < 4; ++j)
#pragma unroll
            for (int q = 0; q < 4; ++q) acc[i][j][q] = 0.0f;

    const int Lrow = tid >> 1;
    const int Lc = (tid & 1) * 4;
    const int arow = bn + Lrow;
    const int brow = bm + Lrow;

    auto issue_chunk = [&](int c, int stage) {
        const int k0 = c * KC;
        const uint32_t st = sbase + stage * STAGE_B;
        const uint32_t soff = (uint32_t)Lrow * ROWB + Lc * 16;
        const __half* pa = A + (size_t)arow * GK + k0 + Lc * 8;
        const __half* pb = B + (size_t)brow * GK + k0 + Lc * 8;
#pragma unroll
        for (int q = 0; q < 4; ++q) {
            cp_async16(st + soff + q * 16, pa + q * 8);
            cp_async16(st + TILE_B + soff + q * 16, pb + q * 8);
        }
        asm volatile("cp.async.commit_group;" ::: "memory");
    };

    issue_chunk(0, 0);
    issue_chunk(1, 1);

    const int NCH = GK / KC;     // 16
    for (int c = 0; c < NCH; ++c) {
        if (c + 1 < NCH) { asm volatile("cp.async.wait_group 1;" ::: "memory"); }
        else             { asm volatile("cp.async.wait_group 0;" ::: "memory"); }
        __syncthreads();
        if (c + 2 < NCH) issue_chunk(c + 2, (c + 2) % NSTAGE);

        const uint32_t st = sbase + (c % NSTAGE) * STAGE_B;
        const uint32_t a_base = st + (uint32_t)(warp_m * 64 + lrow) * ROWB + lchunk;
        const uint32_t b_base = st + TILE_B + (uint32_t)(warp_n * 32 + lrow) * ROWB + lchunk;

#pragma unroll
        for (int s = 0; s < 4; ++s) {
            uint32_t ah[4][4];
#pragma unroll
            for (int i = 0; i < 4; ++i) {
                uint32_t ad = a_base + (uint32_t)i * 16 * ROWB + s * 32;
                ldm_x4(ah[i][0], ah[i][1], ah[i][2], ah[i][3], ad);
            }
            uint32_t bh[2][4];
#pragma unroll
            for (int j2 = 0; j2 < 2; ++j2) {
                uint32_t bd = b_base + (uint32_t)j2 * 16 * ROWB + s * 32;
                ldm_x4(bh[j2][0], bh[j2][1], bh[j2][2], bh[j2][3], bd);
            }
#pragma unroll
            for (int i = 0; i < 4; ++i) {
#pragma unroll
                for (int j = 0; j < 4; ++j) {
                    const int j2 = j >> 1, sel = j & 1;
                    mma16816(acc[i][j], ah[i][0], ah[i][1], ah[i][2], ah[i][3],
                             bh[j2][sel], bh[j2][sel + 2]);
                }
            }
        }
    }

#pragma unroll
    for (int i = 0; i < 4; ++i) {
#pragma unroll
        for (int j = 0; j < 4; ++j) {
            const int row0 = bn + warp_m * 64 + i * 16 + (lane >> 2);
            const int col = bm + warp_n * 32 + j * 8 + (lane & 3) * 2;
            const float2 bv = *(const float2*)(bias + col);
            float o00 = acc[i][j][0] + bv.x, o01 = acc[i][j][1] + bv.y;
            float o10 = acc[i][j][2] + bv.x, o11 = acc[i][j][3] + bv.y;
            if (HALF_OUT) {
                *(__half2*)(Ch + (size_t)row0 * Mcols + col) =
                    __halves2half2(__float2half_rn(o00), __float2half_rn(o01));
                *(__half2*)(Ch + (size_t)(row0 + 8) * Mcols + col) =
                    __halves2half2(__float2half_rn(o10), __float2half_rn(o11));
            } else {
                *(float2*)(C + (size_t)row0 * Mcols + col) = make_float2(o00, o01);
                *(float2*)(C + (size_t)(row0 + 8) * Mcols + col) = make_float2(o10, o11);
            }
        }
    }
}

// fused Q/K/V projection: grid (8, 128, 3); z selects weight/bias/output
__global__ void __launch_bounds__(256, 2)
gemm_qkv(const __half* __restrict__ A, const __half* __restrict__ W,
         const float* __restrict__ bq, const float* __restrict__ bk,
         const float* __restrict__ bv,
         __half* __restrict__ Q, __half* __restrict__ K, __half* __restrict__ V) {
    const int which = blockIdx.z;
    const __half* B = W + (size_t)which * DD * DD;
    const float* bias = (which == 0) ? bq : (which == 1) ? bk : bv;
    __half* Ch = (which == 0) ? Q : (which == 1) ? K : V;
    gemm_core<1>(A, B, bias, nullptr, Ch, DD);
}
__global__ void __launch_bounds__(256, 2)
gemm_mma_f32(const __half* A, const __half* B,
             const float* bias, float* C, int Mcols) {
    gemm_core<0>(A, B, bias, C, nullptr, Mcols);
}

// ---------------------------------------------------------------------------
// phi body: P[bh, s, fc*128 + .] = softplus(In[bs, h] @ rf[h]) ; 256 thr.
// ---------------------------------------------------------------------------
#define PH_QS 144
#define PH_RS 272
#define PH_RFH (128 * PH_QS)                // 18432
#define PH_DSMEM (PH_RFH + 64 * PH_RS)      // 35840

__device__ __forceinline__ void phi_body(
    const __half* __restrict__ In, const __half* __restrict__ RFh,
    __half* __restrict__ Ph, int stile, int fc, int bh, char* dsm) {
    const uint32_t sb = smem_u32(dsm);
    const int tid = threadIdx.x;
    const int wid = tid >> 5, lane = tid & 31;
    const int b = bh >> 4, h = bh & 15;
    const int s0 = stile * 128;

    {
        const int r = tid >> 1, c0 = (tid & 1) * 4;
        const __half* ph = In + ((size_t)(b * SS + s0 + r)) * DD + h * HD + c0 * 8;
        const uint32_t so = sb + (uint32_t)r * PH_QS + c0 * 16;
#pragma unroll
        for (int q = 0; q < 4; ++q) cp_async16(so + q * 16, ph + q * 8);
    }
    {
        const int r = tid >> 2, c0 = (tid & 3) * 4;
        const __half* ph = RFh + (size_t)h * HD * FF + (size_t)r * FF + fc * 128 + c0 * 8;
        const uint32_t so = sb + PH_RFH + (uint32_t)r * PH_RS + c0 * 16;
#pragma unroll
        for (int q = 0; q < 4; ++q) cp_async16(so + q * 16, ph + q * 8);
    }
    asm volatile("cp.async.commit_group;" ::: "memory");
    asm volatile("cp.async.wait_group 0;" ::: "memory");
    __syncthreads();

    float acc[16][4];
#pragma unroll
    for (int j = 0; j < 16; ++j)
#pragma unroll
        for (int q = 0; q < 4; ++q) acc[j][q] = 0.0f;

    const int lrow = lane & 15, lch = (lane >> 4) * 16;
    const uint32_t a_base = sb + (uint32_t)(wid * 16 + lrow) * PH_QS + lch;

#pragma unroll
    for (int ks = 0; ks < 4; ++ks) {
        uint32_t ah[4];
        ldm_x4(ah[0], ah[1], ah[2], ah[3], a_base + ks * 32);
#pragma unroll
        for (int ft = 0; ft < 8; ++ft) {
            uint32_t bh4[4];
            uint32_t bd = taddr(sb + PH_RFH, PH_RS, ks * 16, ft * 16, lane);
            ldm_x4_t(bh4[0], bh4[1], bh4[2], bh4[3], bd);
#pragma unroll
            for (int sel = 0; sel < 2; ++sel) {
                const int j = ft * 2 + sel;
                mma16816(acc[j], ah[0], ah[1], ah[2], ah[3], bh4[sel], bh4[sel + 2]);
            }
        }
    }

    const int r0 = wid * 16 + (lane >> 2);
#pragma unroll
    for (int j = 0; j < 16; ++j) {
        const int col = fc * 128 + j * 8 + (lane & 3) * 2;
        float s00 = softplusf(acc[j][0]), s01 = softplusf(acc[j][1]);
        float s10 = softplusf(acc[j][2]), s11 = softplusf(acc[j][3]);
        size_t o0 = ((size_t)bh * SS + s0 + r0) * FF + col;
        size_t o1 = ((size_t)bh * SS + s0 + r0 + 8) * FF + col;
        *(__half2*)(Ph + o0) = __halves2half2(__float2half_rn(s00), __float2half_rn(s01));
        *(__half2*)(Ph + o1) = __halves2half2(__float2half_rn(s10), __float2half_rn(s11));
    }
}

// ---------------------------------------------------------------------------
// kv body: kv[f,d] += sum_s kp[s,f]*v[s,d]; ksum via ones column (col 64 of V).
// ---------------------------------------------------------------------------
#define KV_KS 528
#define KV_VS 144
#define KV_KH 0
#define KV_VH 16896
#define KV_STG (KV_VH + 32 * KV_VS + 32)  // 21536
#define KV_DSMEM (2 * KV_STG)             // 43072

__device__ __forceinline__ void kv_body(
    const __half* __restrict__ Kph, const __half* __restrict__ Vh,
    float* __restrict__ kv, float* __restrict__ ksum,
    int chunk, int h, int b, char* dsm) {
    const uint32_t sb = smem_u32(dsm);
    const int tid = threadIdx.x;
    const int wid = tid >> 5, lane = tid & 31;
    const int bh = b * HH + h;
    const int sbase0 = chunk * 512;

    if (tid < 64) {
        const int stg = tid >> 5, r = tid & 31;
        const uint32_t bvh = sb + stg * KV_STG + KV_VH + r * KV_VS + 128;
        asm volatile("st.shared.v4.b32 [%0], {%1,%2,%3,%4};"
                     :: "r"(bvh), "r"(0x00003C00u), "r"(0u), "r"(0u), "r"(0u));
    }

    auto issue = [&](int t, int stg) {
        const int s0 = sbase0 + t * 32;
        const uint32_t st = sb + stg * KV_STG;
        const int r = tid >> 3;
        {
            const int c0 = (tid & 7) * 4;
            const __half* ph = Kph + ((size_t)bh * SS + s0 + r) * FF + c0 * 8;
            const uint32_t so = st + (uint32_t)r * KV_KS + c0 * 16;
#pragma unroll
            for (int q = 0; q < 4; ++q) cp_async16(so + q * 16, ph + q * 8);
        }
        {
            const int c = tid & 7;
            const __half* ph = Vh + ((size_t)(b * SS + s0 + r)) * DD + h * HD + c * 8;
            cp_async16(st + KV_VH + (uint32_t)r * KV_VS + c * 16, ph);
        }
        asm volatile("cp.async.commit_group;" ::: "memory");
    };

    float acc[2][9][4];
#pragma unroll
    for (int i = 0; i < 2; ++i)
#pragma unroll
        for (int j = 0; j < 9; ++j)
#pragma unroll
            for (int q = 0; q < 4; ++q) acc[i][j][q] = 0.0f;

    issue(0, 0);
    for (int t = 0; t < 16; ++t) {
        if (t + 1 < 16) issue(t + 1, (t + 1) & 1);
        if (t + 1 < 16) { asm volatile("cp.async.wait_group 1;" ::: "memory"); }
        else            { asm volatile("cp.async.wait_group 0;" ::: "memory"); }
        __syncthreads();
        const uint32_t st = sb + (t & 1) * KV_STG;

#pragma unroll
        for (int ks = 0; ks < 2; ++ks) {
            uint32_t ah[2][4];
#pragma unroll
            for (int mt = 0; mt < 2; ++mt) {
                uint32_t ad = taddr(st + KV_KH, KV_KS, ks * 16, wid * 32 + mt * 16, lane);
                ldm_x4_t(ah[mt][0], ah[mt][1], ah[mt][2], ah[mt][3], ad);
            }
#pragma unroll
            for (int dg = 0; dg < 5; ++dg) {
                uint32_t bh4[4];
                uint32_t bd = taddr(st + KV_VH, KV_VS, ks * 16, dg * 16, lane);
                ldm_x4_t(bh4[0], bh4[1], bh4[2], bh4[3], bd);
                const int nsel = (dg == 4) ? 1 : 2;
#pragma unroll
                for (int mt = 0; mt < 2; ++mt) {
#pragma unroll
                    for (int sel = 0; sel < 2; ++sel) {
                        if (sel >= nsel) continue;
                        const int j = dg * 2 + sel;
                        mma16816(acc[mt][j], ah[mt][0], ah[mt][1], ah[mt][2], ah[mt][3],
                                 bh4[sel], bh4[sel + 2]);
                    }
                }
            }
        }
        __syncthreads();
    }

    float* kvp = kv + (size_t)bh * FF * HD;
#pragma unroll
    for (int mt = 0; mt < 2; ++mt) {
        const int f0 = wid * 32 + mt * 16 + (lane >> 2);
#pragma unroll
        for (int j = 0; j < 8; ++j) {
            const int d0 = j * 8 + (lane & 3) * 2;
            atomicAdd(&kvp[f0 * HD + d0],       acc[mt][j][0]);
            atomicAdd(&kvp[f0 * HD + d0 + 1],   acc[mt][j][1]);
            atomicAdd(&kvp[(f0 + 8) * HD + d0],     acc[mt][j][2]);
            atomicAdd(&kvp[(f0 + 8) * HD + d0 + 1], acc[mt][j][3]);
        }
        if ((lane & 3) == 0) {
            atomicAdd(&ksum[(size_t)bh * FF + f0],     acc[mt][8][0]);
            atomicAdd(&ksum[(size_t)bh * FF + f0 + 8], acc[mt][8][2]);
        }
    }
}

// ---------------------------------------------------------------------------
// phi k' kernel ; fused [kv + phi q'] kernel (kv CTAs first for early start)
// ---------------------------------------------------------------------------
__global__ void __launch_bounds__(256)
phi_k(const __half* __restrict__ Kh, const __half* __restrict__ RFh,
      __half* __restrict__ Pk) {
    extern __shared__ char dsm[];
    phi_body(Kh, RFh, Pk, blockIdx.x, blockIdx.y, blockIdx.z, dsm);
}

#define FUSED_DSMEM (KV_DSMEM > PH_DSMEM ? KV_DSMEM : PH_DSMEM)   // 43072

__global__ void __launch_bounds__(256)
kv_phiq(const __half* __restrict__ Kph, const __half* __restrict__ Vh,
        float* __restrict__ kv, float* __restrict__ ksum,
        const __half* __restrict__ Qh, const __half* __restrict__ RFh,
        __half* __restrict__ Pq) {
    extern __shared__ char dsm[];
    const int cta = blockIdx.x;
    if (cta < 512) {
        // kv: chunk 0..7, h 0..15, b 0..3
        kv_body(Kph, Vh, kv, ksum, cta & 7, (cta >> 3) & 15, cta >> 7, dsm);
    } else {
        // phi q': stile 0..31, fc 0..1, bh 0..63
        const int idx = cta - 512;
        phi_body(Qh, RFh, Pq, idx & 31, (idx >> 5) & 1, idx >> 6, dsm);
    }
}

// ---------------------------------------------------------------------------
// split_kvx: kv fp32 (64 cols) + ksum split (cols 64/65) + zeros -> fp16 [.][72]
// ---------------------------------------------------------------------------
__global__ void __launch_bounds__(256)
split_kvx(const float* __restrict__ kv, const float* __restrict__ ksum,
          __half* __restrict__ kvxh) {
    const int idx = blockIdx.x * 256 + threadIdx.x;    // (bh*256 + f)
    if (idx >= BB * HH * FF) return;
    const float* src = kv + (size_t)idx * HD;
    __half* dh = kvxh + (size_t)idx * 72;
#pragma unroll 8
    for (int c = 0; c < 64; ++c) dh[c] = __float2half_rn(src[c]);
    __half h, l;
    split2(ksum[idx], h, l);
    dh[64] = h; dh[65] = l;
#pragma unroll
    for (int c = 66; c < 72; ++c) dh[c] = __float2half_rn(0.0f);
}

// ---------------------------------------------------------------------------
// out_mma: y = (qp @ kvx) / (col64+col65 + 1e-8). fp16 in/out.
// grid (32 stile, 16 h, 4 b), 256 thr. 3-stage q pipeline, single barrier.
// ---------------------------------------------------------------------------
#define OM_KVS 144
#define OM_KVH 0
#define OM_Q (256 * OM_KVS + 64)          // 36928 (+64 slack for dg4 overread)
#define OM_QS 80
#define OM_QSTG 10240                     // q hi only
#define OM_NSTG 3
#define OM_DSMEM (OM_Q + OM_NSTG * OM_QSTG)   // 67648

__global__ void __launch_bounds__(256)
out_mma(const __half* __restrict__ Qph, const __half* __restrict__ KVh,
        __half* __restrict__ Yh) {
    extern __shared__ char dsm[];
    const uint32_t sb = smem_u32(dsm);
    const int tid = threadIdx.x;
    const int wid = tid >> 5, lane = tid & 31;
    const int stile = blockIdx.x, h = blockIdx.y, b = blockIdx.z;
    const int bh = b * HH + h;
    const int s0 = stile * 128;

    auto issue_q = [&](int c) {
        const uint32_t st = sb + OM_Q + (c % OM_NSTG) * OM_QSTG;
#pragma unroll
        for (int q = 0; q < 2; ++q) {
            const int idx = tid * 2 + q;
            const int r = idx >> 2, cc = idx & 3;
            const __half* ph = Qph + ((size_t)bh * SS + s0 + r) * FF + c * 32 + cc * 8;
            cp_async16(st + (uint32_t)r * OM_QS + cc * 16, ph);
        }
        asm volatile("cp.async.commit_group;" ::: "memory");
    };

    {
        const __half* ph = KVh + ((size_t)bh * FF + tid) * 72;
        const uint32_t so = sb + (uint32_t)tid * OM_KVS;
#pragma unroll
        for (int q = 0; q < 9; ++q) cp_async16(so + q * 16, ph + q * 8);
        asm volatile("cp.async.commit_group;" ::: "memory");
    }
    issue_q(0);
    issue_q(1);

    float acc[9][4];
#pragma unroll
    for (int j = 0; j < 9; ++j)
#pragma unroll
        for (int q = 0; q < 4; ++q) acc[j][q] = 0.0f;

    const int lrow = lane & 15, lch = (lane >> 4) * 16;

    for (int c = 0; c < 8; ++c) {
        if (c < 7) { asm volatile("cp.async.wait_group 1;" ::: "memory"); }
        else       { asm volatile("cp.async.wait_group 0;" ::: "memory"); }
        __syncthreads();
        if (c + 2 < 8) issue_q(c + 2);
        const uint32_t qst = sb + OM_Q + (c % OM_NSTG) * OM_QSTG;

#pragma unroll
        for (int ks = 0; ks < 2; ++ks) {
            uint32_t ah[4];
            uint32_t ad = qst + (uint32_t)(wid * 16 + lrow) * OM_QS + lch + ks * 32;
            ldm_x4(ah[0], ah[1], ah[2], ah[3], ad);
#pragma unroll
            for (int dg = 0; dg < 5; ++dg) {
                uint32_t bh4[4];
                uint32_t bd = taddr(sb + OM_KVH, OM_KVS, c * 32 + ks * 16, dg * 16, lane);
                ldm_x4_t(bh4[0], bh4[1], bh4[2], bh4[3], bd);
                const int nsel = (dg == 4) ? 1 : 2;
#pragma unroll
                for (int sel = 0; sel < 2; ++sel) {
                    if (sel >= nsel) continue;
                    const int j = dg * 2 + sel;
                    mma16816(acc[j], ah[0], ah[1], ah[2], ah[3], bh4[sel], bh4[sel + 2]);
                }
            }
        }
    }

    const int r0 = wid * 16 + (lane >> 2);
    const float den0 = __shfl_sync(0xffffffffu, acc[8][0] + acc[8][1], lane & ~3);
    const float den1 = __shfl_sync(0xffffffffu, acc[8][2] + acc[8][3], lane & ~3);
    const float inv0 = 1.0f / (den0 + 1e-8f);
    const float inv1 = 1.0f / (den1 + 1e-8f);
#pragma unroll
    for (int j = 0; j < 8; ++j) {
        const int col = h * HD + j * 8 + (lane & 3) * 2;
        float o00 = acc[j][0] * inv0, o01 = acc[j][1] * inv0;
        float o10 = acc[j][2] * inv1, o11 = acc[j][3] * inv1;
        size_t off0 = ((size_t)(b * SS + s0 + r0)) * DD + col;
        size_t off1 = ((size_t)(b * SS + s0 + r0 + 8)) * DD + col;
        *(__half2*)(Yh + off0) = __halves2half2(__float2half_rn(o00), __float2half_rn(o01));
        *(__half2*)(Yh + off1) = __halves2half2(__float2half_rn(o10), __float2half_rn(o11));
    }
}

// ---------------------------------------------------------------------------
// fused prep: x->fp16 | 4 weights->fp16 | rf->fp16 | zero kv | zero ksum
// block ranges: x [0,16384) w [16384,20480) rf [20480,20736)
//               kvz [20736,21760) ksz [21760,21776)   (kv = 1M floats = 1024 blk)
// ---------------------------------------------------------------------------
__global__ void __launch_bounds__(256)
prep_kernel(const float* __restrict__ x,
            const float* __restrict__ w0, const float* __restrict__ w1,
            const float* __restrict__ w2, const float* __restrict__ w3,
            const float* __restrict__ rf,
            __half* __restrict__ xh, __half* __restrict__ wh,
            __half* __restrict__ rfh,
            float* __restrict__ kv, float* __restrict__ ksum) {
    const int blk = blockIdx.x;
    const int tid = threadIdx.x;
    if (blk < 16384) {
        int i = (blk * 256 + tid) * 4;
        float4 v = *(const float4*)(x + i);
        *(__half2*)(xh + i)     = __halves2half2(__float2half_rn(v.x), __float2half_rn(v.y));
        *(__half2*)(xh + i + 2) = __halves2half2(__float2half_rn(v.z), __float2half_rn(v.w));
    } else if (blk < 20480) {
        int b2 = blk - 16384;
        int which = b2 >> 10;
        const float* src = (which == 0) ? w0 : (which == 1) ? w1 : (which == 2) ? w2 : w3;
        __half* dst = wh + (size_t)which * DD * DD;
        int i = ((b2 & 1023) * 256 + tid) * 4;
        float4 v = *(const float4*)(src + i);
        *(__half2*)(dst + i)     = __halves2half2(__float2half_rn(v.x), __float2half_rn(v.y));
        *(__half2*)(dst + i + 2) = __halves2half2(__float2half_rn(v.z), __float2half_rn(v.w));
    } else if (blk < 20736) {
        int i = ((blk - 20480) * 256 + tid) * 4;
        float4 v = *(const float4*)(rf + i);
        *(__half2*)(rfh + i)     = __halves2half2(__float2half_rn(v.x), __float2half_rn(v.y));
        *(__half2*)(rfh + i + 2) = __halves2half2(__float2half_rn(v.z), __float2half_rn(v.w));
    } else if (blk < 21760) {
        int i = ((blk - 20736) * 256 + tid) * 4;
        *(float4*)(kv + i) = make_float4(0.f, 0.f, 0.f, 0.f);
    } else {
        int i = ((blk - 21760) * 256 + tid) * 4;
        *(float4*)(ksum + i) = make_float4(0.f, 0.f, 0.f, 0.f);
    }
}

// ---------------------------------------------------------------------------
// launch
// ---------------------------------------------------------------------------
extern "C" void kernel_launch(void* const* d_in, const int* in_sizes, int n_in,
                              void* d_out, int out_size) {
    const float* x  = (const float*)d_in[0];
    const float* Wq = (const float*)d_in[1];
    const float* bq = (const float*)d_in[2];
    const float* Wk = (const float*)d_in[3];
    const float* bk = (const float*)d_in[4];
    const float* Wv = (const float*)d_in[5];
    const float* bv = (const float*)d_in[6];
    const float* Wo = (const float*)d_in[7];
    const float* bo = (const float*)d_in[8];
    const float* rf = (const float*)d_in[9];
    float* out = (float*)d_out;

    __half *pxh, *pwh, *prfh, *pqh, *pkh, *pvh, *pyh, *pqph, *pkph, *pkvh;
    float *pkv, *pks;
    cudaGetSymbolAddress((void**)&pxh, g_xh);
    cudaGetSymbolAddress((void**)&pwh, g_wh);
    cudaGetSymbolAddress((void**)&prfh, g_rfh);
    cudaGetSymbolAddress((void**)&pqh, g_qh);
    cudaGetSymbolAddress((void**)&pkh, g_kh);
    cudaGetSymbolAddress((void**)&pvh, g_vh);
    cudaGetSymbolAddress((void**)&pyh, g_yh);
    cudaGetSymbolAddress((void**)&pqph, g_qph);
    cudaGetSymbolAddress((void**)&pkph, g_kph);
    cudaGetSymbolAddress((void**)&pkvh, g_kvh);
    cudaGetSymbolAddress((void**)&pkv, g_kv);
    cudaGetSymbolAddress((void**)&pks, g_ksum);

    cudaFuncSetAttribute(gemm_qkv, cudaFuncAttributeMaxDynamicSharedMemorySize, GEMM_DSMEM);
    cudaFuncSetAttribute(gemm_mma_f32, cudaFuncAttributeMaxDynamicSharedMemorySize, GEMM_DSMEM);
    cudaFuncSetAttribute(phi_k, cudaFuncAttributeMaxDynamicSharedMemorySize, PH_DSMEM);
    cudaFuncSetAttribute(kv_phiq, cudaFuncAttributeMaxDynamicSharedMemorySize, FUSED_DSMEM);
    cudaFuncSetAttribute(out_mma, cudaFuncAttributeMaxDynamicSharedMemorySize, OM_DSMEM);

    const int WSZ = DD * DD;

    prep_kernel<<<21776, 256>>>(x, Wq, Wk, Wv, Wo, rf, pxh, pwh, prfh, pkv, pks);

    // fused Q/K/V projections
    gemm_qkv<<<dim3(DD / 128, NN / 128, 3), 256, GEMM_DSMEM>>>(
        pxh, pwh, bq, bk, bv, pqh, pkh, pvh);

    // k' feature map first (kv depends on it)
    phi_k<<<dim3(SS / 128, 2, BB * HH), 256, PH_DSMEM>>>(pkh, prfh, pkph);

    // fused: kv aggregation (blocks 0..511, start first) + q' feature map
    kv_phiq<<<512 + 4096, 256, FUSED_DSMEM>>>(
        pkph, pvh, pkv, pks, pqh, prfh, pqph);

    split_kvx<<<(BB * HH * FF + 255) / 256, 256>>>(pkv, pks, pkvh);

    out_mma<<<dim3(SS / 128, HH, BB), 256, OM_DSMEM>>>(pqph, pkvh, pyh);

    gemm_mma_f32<<<dim3(DD / 128, NN / 128), 256, GEMM_DSMEM>>>(
        pyh, pwh + 3 * WSZ, bo, out, DD);
}

// round 17
// speedup vs baseline: 1.0234x; 1.0234x over previous
#include <cuda_runtime.h>
#include <cuda_fp16.h>
#include <math.h>
#include <stdint.h>

// ---------------------------------------------------------------------------
// Problem constants
// ---------------------------------------------------------------------------
#define BB 4
#define SS 4096
#define DD 1024
#define HH 16
#define FF 256
#define HD 64
#define NN (BB * SS)          // 16384 rows
#define GK 1024               // GEMM K

// ---------------------------------------------------------------------------
// Scratch (device globals; no allocations allowed). Pure fp16 operands;
// only kv/ksum accumulate in fp32 (atomics), ksum re-split into kvx cols 64/65.
// ---------------------------------------------------------------------------
__device__ __half g_xh[NN * DD];
__device__ __half g_wh[4 * DD * DD];
__device__ __half g_rfh[HH * HD * FF];

__device__ __half g_qh[NN * DD];
__device__ __half g_kh[NN * DD];
__device__ __half g_vh[NN * DD];
__device__ __half g_yh[NN * DD];

__device__ __half g_qph[(size_t)BB * HH * SS * FF];
__device__ __half g_kph[(size_t)BB * HH * SS * FF];

__device__ float g_kv[(size_t)BB * HH * FF * HD];     // fp32 (atomics)
__device__ float g_ksum[(size_t)BB * HH * FF];
// extended kv: 72 cols = kv(64) | ksum_hi(64) ksum_lo(65) | zeros(66-71)
__device__ __half g_kvh[(size_t)BB * HH * FF * 72];

// ---------------------------------------------------------------------------
// PTX helpers (base-target: cp.async / ldmatrix / mma.sync)
// ---------------------------------------------------------------------------
__device__ __forceinline__ uint32_t smem_u32(const void* p) {
    return (uint32_t)__cvta_generic_to_shared(p);
}
__device__ __forceinline__ void cp_async16(uint32_t dst, const void* src) {
    asm volatile("cp.async.cg.shared.global [%0], [%1], 16;"
                 :: "r"(dst), "l"(src) : "memory");
}
__device__ __forceinline__ void ldm_x4(uint32_t& r0, uint32_t& r1,
                                       uint32_t& r2, uint32_t& r3, uint32_t addr) {
    asm volatile("ldmatrix.sync.aligned.m8n8.x4.shared.b16 {%0,%1,%2,%3}, [%4];"
                 : "=r"(r0), "=r"(r1), "=r"(r2), "=r"(r3) : "r"(addr));
}
__device__ __forceinline__ void ldm_x4_t(uint32_t& r0, uint32_t& r1,
                                         uint32_t& r2, uint32_t& r3, uint32_t addr) {
    asm volatile("ldmatrix.sync.aligned.m8n8.x4.trans.shared.b16 {%0,%1,%2,%3}, [%4];"
                 : "=r"(r0), "=r"(r1), "=r"(r2), "=r"(r3) : "r"(addr));
}
__device__ __forceinline__ void mma16816(float* c, uint32_t a0, uint32_t a1,
                                         uint32_t a2, uint32_t a3,
                                         uint32_t b0, uint32_t b1) {
    asm volatile(
        "mma.sync.aligned.m16n8k16.row.col.f32.f16.f16.f32 "
        "{%0,%1,%2,%3}, {%4,%5,%6,%7}, {%8,%9}, {%0,%1,%2,%3};"
        : "+f"(c[0]), "+f"(c[1]), "+f"(c[2]), "+f"(c[3])
        : "r"(a0), "r"(a1), "r"(a2), "r"(a3), "r"(b0), "r"(b1));
}
__device__ __forceinline__ uint32_t taddr(uint32_t base, int stride,
                                          int k0, int col0, int lane) {
    int g = lane >> 3, r = lane & 7;
    return base + (uint32_t)((k0 + ((g >> 1) << 3) + r) * stride
                             + (col0 + ((g & 1) << 3)) * 2);
}
__device__ __forceinline__ void split2(float v, __half& h, __half& l) {
    h = __float2half_rn(v);
    l = __float2half_rn(v - __half2float(h));
}
__device__ __forceinline__ float softplusf(float x) {
    return fmaxf(x, 0.0f) + log1pf(expf(-fabsf(x)));
}

// ---------------------------------------------------------------------------
// HMMA single-pass fp16 GEMM-NT: C = A @ B^T + bias.
// 128x128x64 CTA tile, 2 smem tiles per stage (A, B), 3 stages
// -> 110.6 KB smem -> 2 CTAs/SM. Single barrier per chunk, issue-before-compute.
// ---------------------------------------------------------------------------
#define KC 64
#define ROWB 144                         // 128B data + 16B pad; 9 mod 8 = 1
#define TILE_B (128 * ROWB)              // 18432
#define STAGE_B (2 * TILE_B)             // 36864 (A, B)
#define NSTAGE 3
#define GEMM_DSMEM (NSTAGE * STAGE_B)    // 110592 B

template <int HALF_OUT>
__device__ __forceinline__ void gemm_core(
    const __half* __restrict__ A, const __half* __restrict__ B,
    const float* __restrict__ bias, float* __restrict__ C,
    __half* __restrict__ Ch, int Mcols) {
    extern __shared__ char dsm[];
    const uint32_t sbase = smem_u32(dsm);

    const int tid = threadIdx.x;
    const int wid = tid >> 5, lane = tid & 31;
    const int warp_m = wid >> 2;
    const int warp_n = wid & 3;
    const int bm = blockIdx.x * 128;
    const int bn = blockIdx.y * 128;

    const int lrow = lane & 15;
    const int lchunk = (lane >> 4) * 16;

    float acc[4][4][4];
#pragma unroll
    for (int i = 0; i < 4; ++i)
#pragma unroll
        for (int j = 0; j < 4; ++j)
#pragma unroll
            for (int q = 0; q < 4; ++q) acc[i][j][q] = 0.0f;

    const int Lrow = tid >> 1;
    const int Lc = (tid & 1) * 4;
    const int arow = bn + Lrow;
    const int brow = bm + Lrow;

    auto issue_chunk = [&](int c, int stage) {
        const int k0 = c * KC;
        const uint32_t st = sbase + stage * STAGE_B;
        const uint32_t soff = (uint32_t)Lrow * ROWB + Lc * 16;
        const __half* pa = A + (size_t)arow * GK + k0 + Lc * 8;
        const __half* pb = B + (size_t)brow * GK + k0 + Lc * 8;
#pragma unroll
        for (int q = 0; q < 4; ++q) {
            cp_async16(st + soff + q * 16, pa + q * 8);
            cp_async16(st + TILE_B + soff + q * 16, pb + q * 8);
        }
        asm volatile("cp.async.commit_group;" ::: "memory");
    };

    issue_chunk(0, 0);
    issue_chunk(1, 1);

    const int NCH = GK / KC;     // 16
    for (int c = 0; c < NCH; ++c) {
        if (c + 1 < NCH) { asm volatile("cp.async.wait_group 1;" ::: "memory"); }
        else             { asm volatile("cp.async.wait_group 0;" ::: "memory"); }
        __syncthreads();
        if (c + 2 < NCH) issue_chunk(c + 2, (c + 2) % NSTAGE);

        const uint32_t st = sbase + (c % NSTAGE) * STAGE_B;
        const uint32_t a_base = st + (uint32_t)(warp_m * 64 + lrow) * ROWB + lchunk;
        const uint32_t b_base = st + TILE_B + (uint32_t)(warp_n * 32 + lrow) * ROWB + lchunk;

#pragma unroll
        for (int s = 0; s < 4; ++s) {
            uint32_t ah[4][4];
#pragma unroll
            for (int i = 0; i < 4; ++i) {
                uint32_t ad = a_base + (uint32_t)i * 16 * ROWB + s * 32;
                ldm_x4(ah[i][0], ah[i][1], ah[i][2], ah[i][3], ad);
            }
            uint32_t bh[2][4];
#pragma unroll
            for (int j2 = 0; j2 < 2; ++j2) {
                uint32_t bd = b_base + (uint32_t)j2 * 16 * ROWB + s * 32;
                ldm_x4(bh[j2][0], bh[j2][1], bh[j2][2], bh[j2][3], bd);
            }
#pragma unroll
            for (int i = 0; i < 4; ++i) {
#pragma unroll
                for (int j = 0; j < 4; ++j) {
                    const int j2 = j >> 1, sel = j & 1;
                    mma16816(acc[i][j], ah[i][0], ah[i][1], ah[i][2], ah[i][3],
                             bh[j2][sel], bh[j2][sel + 2]);
                }
            }
        }
    }

#pragma unroll
    for (int i = 0; i < 4; ++i) {
#pragma unroll
        for (int j = 0; j < 4; ++j) {
            const int row0 = bn + warp_m * 64 + i * 16 + (lane >> 2);
            const int col = bm + warp_n * 32 + j * 8 + (lane & 3) * 2;
            const float2 bv = *(const float2*)(bias + col);
            float o00 = acc[i][j][0] + bv.x, o01 = acc[i][j][1] + bv.y;
            float o10 = acc[i][j][2] + bv.x, o11 = acc[i][j][3] + bv.y;
            if (HALF_OUT) {
                *(__half2*)(Ch + (size_t)row0 * Mcols + col) =
                    __halves2half2(__float2half_rn(o00), __float2half_rn(o01));
                *(__half2*)(Ch + (size_t)(row0 + 8) * Mcols + col) =
                    __halves2half2(__float2half_rn(o10), __float2half_rn(o11));
            } else {
                *(float2*)(C + (size_t)row0 * Mcols + col) = make_float2(o00, o01);
                *(float2*)(C + (size_t)(row0 + 8) * Mcols + col) = make_float2(o10, o11);
            }
        }
    }
}

// fused Q/K/V projection: grid (8, 128, 3); z selects weight/bias/output
__global__ void __launch_bounds__(256, 2)
gemm_qkv(const __half* __restrict__ A, const __half* __restrict__ W,
         const float* __restrict__ bq, const float* __restrict__ bk,
         const float* __restrict__ bv,
         __half* __restrict__ Q, __half* __restrict__ K, __half* __restrict__ V) {
    const int which = blockIdx.z;
    const __half* B = W + (size_t)which * DD * DD;
    const float* bias = (which == 0) ? bq : (which == 1) ? bk : bv;
    __half* Ch = (which == 0) ? Q : (which == 1) ? K : V;
    gemm_core<1>(A, B, bias, nullptr, Ch, DD);
}
__global__ void __launch_bounds__(256, 2)
gemm_mma_f32(const __half* A, const __half* B,
             const float* bias, float* C, int Mcols) {
    gemm_core<0>(A, B, bias, C, nullptr, Mcols);
}

// ---------------------------------------------------------------------------
// phi_mma: qp = softplus(q @ rf), fp16 in/out. FUSED q'/k' launch:
// grid (32 stile, 2 fchunk, 128): z = path*64 + bh. CTA: 128s x 128f, K=64.
// ---------------------------------------------------------------------------
#define PH_QS 144
#define PH_RS 272
#define PH_RFH (128 * PH_QS)                // 18432
#define PH_DSMEM (PH_RFH + 64 * PH_RS)      // 35840

__global__ void __launch_bounds__(256)
phi_mma(const __half* __restrict__ Qh, const __half* __restrict__ Kh,
        const __half* __restrict__ RFh,
        __half* __restrict__ Pq, __half* __restrict__ Pk) {
    extern __shared__ char dsm[];
    const uint32_t sb = smem_u32(dsm);
    const int tid = threadIdx.x;
    const int wid = tid >> 5, lane = tid & 31;
    const int stile = blockIdx.x, fc = blockIdx.y;
    const int zz = blockIdx.z;
    const int bh = zz & 63;
    const __half* In = (zz < 64) ? Qh : Kh;
    __half* Ph = (zz < 64) ? Pq : Pk;
    const int b = bh >> 4, h = bh & 15;
    const int s0 = stile * 128;

    {
        const int r = tid >> 1, c0 = (tid & 1) * 4;
        const __half* ph = In + ((size_t)(b * SS + s0 + r)) * DD + h * HD + c0 * 8;
        const uint32_t so = sb + (uint32_t)r * PH_QS + c0 * 16;
#pragma unroll
        for (int q = 0; q < 4; ++q) cp_async16(so + q * 16, ph + q * 8);
    }
    {
        const int r = tid >> 2, c0 = (tid & 3) * 4;
        const __half* ph = RFh + (size_t)h * HD * FF + (size_t)r * FF + fc * 128 + c0 * 8;
        const uint32_t so = sb + PH_RFH + (uint32_t)r * PH_RS + c0 * 16;
#pragma unroll
        for (int q = 0; q < 4; ++q) cp_async16(so + q * 16, ph + q * 8);
    }
    asm volatile("cp.async.commit_group;" ::: "memory");
    asm volatile("cp.async.wait_group 0;" ::: "memory");
    __syncthreads();

    float acc[16][4];
#pragma unroll
    for (int j = 0; j < 16; ++j)
#pragma unroll
        for (int q = 0; q < 4; ++q) acc[j][q] = 0.0f;

    const int lrow = lane & 15, lch = (lane >> 4) * 16;
    const uint32_t a_base = sb + (uint32_t)(wid * 16 + lrow) * PH_QS + lch;

#pragma unroll
    for (int ks = 0; ks < 4; ++ks) {
        uint32_t ah[4];
        ldm_x4(ah[0], ah[1], ah[2], ah[3], a_base + ks * 32);
#pragma unroll
        for (int ft = 0; ft < 8; ++ft) {
            uint32_t bh4[4];
            uint32_t bd = taddr(sb + PH_RFH, PH_RS, ks * 16, ft * 16, lane);
            ldm_x4_t(bh4[0], bh4[1], bh4[2], bh4[3], bd);
#pragma unroll
            for (int sel = 0; sel < 2; ++sel) {
                const int j = ft * 2 + sel;
                mma16816(acc[j], ah[0], ah[1], ah[2], ah[3], bh4[sel], bh4[sel + 2]);
            }
        }
    }

    const int r0 = wid * 16 + (lane >> 2);
#pragma unroll
    for (int j = 0; j < 16; ++j) {
        const int col = fc * 128 + j * 8 + (lane & 3) * 2;
        float s00 = softplusf(acc[j][0]), s01 = softplusf(acc[j][1]);
        float s10 = softplusf(acc[j][2]), s11 = softplusf(acc[j][3]);
        size_t o0 = ((size_t)bh * SS + s0 + r0) * FF + col;
        size_t o1 = ((size_t)bh * SS + s0 + r0 + 8) * FF + col;
        *(__half2*)(Ph + o0) = __halves2half2(__float2half_rn(s00), __float2half_rn(s01));
        *(__half2*)(Ph + o1) = __halves2half2(__float2half_rn(s10), __float2half_rn(s11));
    }
}

// ---------------------------------------------------------------------------
// kv_mma: kv[f,d] += sum_s kp[s,f]*v[s,d]; ksum via ones column (col 64 of V).
// fp16 in, fp32 atomics out. grid (8, 16, 4), 256 thr.
// ---------------------------------------------------------------------------
#define KV_KS 528
#define KV_VS 144
#define KV_KH 0
#define KV_VH 16896
#define KV_STG (KV_VH + 32 * KV_VS + 32)  // 21536
#define KV_DSMEM (2 * KV_STG)             // 43072

__global__ void __launch_bounds__(256)
kv_mma(const __half* __restrict__ Kph, const __half* __restrict__ Vh,
       float* __restrict__ kv, float* __restrict__ ksum) {
    extern __shared__ char dsm[];
    const uint32_t sb = smem_u32(dsm);
    const int tid = threadIdx.x;
    const int wid = tid >> 5, lane = tid & 31;
    const int chunk = blockIdx.x, h = blockIdx.y, b = blockIdx.z;
    const int bh = b * HH + h;
    const int sbase0 = chunk * 512;

    if (tid < 64) {
        const int stg = tid >> 5, r = tid & 31;
        const uint32_t bvh = sb + stg * KV_STG + KV_VH + r * KV_VS + 128;
        asm volatile("st.shared.v4.b32 [%0], {%1,%2,%3,%4};"
                     :: "r"(bvh), "r"(0x00003C00u), "r"(0u), "r"(0u), "r"(0u));
    }

    auto issue = [&](int t, int stg) {
        const int s0 = sbase0 + t * 32;
        const uint32_t st = sb + stg * KV_STG;
        const int r = tid >> 3;
        {
            const int c0 = (tid & 7) * 4;
            const __half* ph = Kph + ((size_t)bh * SS + s0 + r) * FF + c0 * 8;
            const uint32_t so = st + (uint32_t)r * KV_KS + c0 * 16;
#pragma unroll
            for (int q = 0; q < 4; ++q) cp_async16(so + q * 16, ph + q * 8);
        }
        {
            const int c = tid & 7;
            const __half* ph = Vh + ((size_t)(b * SS + s0 + r)) * DD + h * HD + c * 8;
            cp_async16(st + KV_VH + (uint32_t)r * KV_VS + c * 16, ph);
        }
        asm volatile("cp.async.commit_group;" ::: "memory");
    };

    float acc[2][9][4];
#pragma unroll
    for (int i = 0; i < 2; ++i)
#pragma unroll
        for (int j = 0; j < 9; ++j)
#pragma unroll
            for (int q = 0; q < 4; ++q) acc[i][j][q] = 0.0f;

    issue(0, 0);
    for (int t = 0; t < 16; ++t) {
        if (t + 1 < 16) issue(t + 1, (t + 1) & 1);
        if (t + 1 < 16) { asm volatile("cp.async.wait_group 1;" ::: "memory"); }
        else            { asm volatile("cp.async.wait_group 0;" ::: "memory"); }
        __syncthreads();
        const uint32_t st = sb + (t & 1) * KV_STG;

#pragma unroll
        for (int ks = 0; ks < 2; ++ks) {
            uint32_t ah[2][4];
#pragma unroll
            for (int mt = 0; mt < 2; ++mt) {
                uint32_t ad = taddr(st + KV_KH, KV_KS, ks * 16, wid * 32 + mt * 16, lane);
                ldm_x4_t(ah[mt][0], ah[mt][1], ah[mt][2], ah[mt][3], ad);
            }
#pragma unroll
            for (int dg = 0; dg < 5; ++dg) {
                uint32_t bh4[4];
                uint32_t bd = taddr(st + KV_VH, KV_VS, ks * 16, dg * 16, lane);
                ldm_x4_t(bh4[0], bh4[1], bh4[2], bh4[3], bd);
                const int nsel = (dg == 4) ? 1 : 2;
#pragma unroll
                for (int mt = 0; mt < 2; ++mt) {
#pragma unroll
                    for (int sel = 0; sel < 2; ++sel) {
                        if (sel >= nsel) continue;
                        const int j = dg * 2 + sel;
                        mma16816(acc[mt][j], ah[mt][0], ah[mt][1], ah[mt][2], ah[mt][3],
                                 bh4[sel], bh4[sel + 2]);
                    }
                }
            }
        }
        __syncthreads();
    }

    float* kvp = kv + (size_t)bh * FF * HD;
#pragma unroll
    for (int mt = 0; mt < 2; ++mt) {
        const int f0 = wid * 32 + mt * 16 + (lane >> 2);
#pragma unroll
        for (int j = 0; j < 8; ++j) {
            const int d0 = j * 8 + (lane & 3) * 2;
            atomicAdd(&kvp[f0 * HD + d0],       acc[mt][j][0]);
            atomicAdd(&kvp[f0 * HD + d0 + 1],   acc[mt][j][1]);
            atomicAdd(&kvp[(f0 + 8) * HD + d0],     acc[mt][j][2]);
            atomicAdd(&kvp[(f0 + 8) * HD + d0 + 1], acc[mt][j][3]);
        }
        if ((lane & 3) == 0) {
            atomicAdd(&ksum[(size_t)bh * FF + f0],     acc[mt][8][0]);
            atomicAdd(&ksum[(size_t)bh * FF + f0 + 8], acc[mt][8][2]);
        }
    }
}

// ---------------------------------------------------------------------------
// split_kvx: kv fp32 (64 cols) + ksum split (cols 64/65) + zeros -> fp16 [.][72]
// ---------------------------------------------------------------------------
__global__ void __launch_bounds__(256)
split_kvx(const float* __restrict__ kv, const float* __restrict__ ksum,
          __half* __restrict__ kvxh) {
    const int idx = blockIdx.x * 256 + threadIdx.x;    // (bh*256 + f)
    if (idx >= BB * HH * FF) return;
    const float* src = kv + (size_t)idx * HD;
    __half* dh = kvxh + (size_t)idx * 72;
#pragma unroll 8
    for (int c = 0; c < 64; ++c) dh[c] = __float2half_rn(src[c]);
    __half h, l;
    split2(ksum[idx], h, l);
    dh[64] = h; dh[65] = l;
#pragma unroll
    for (int c = 66; c < 72; ++c) dh[c] = __float2half_rn(0.0f);
}

// ---------------------------------------------------------------------------
// out_mma: y = (qp @ kvx) / (col64+col65 + 1e-8). fp16 in/out.
// grid (32 stile, 16 h, 4 b), 256 thr. 3-stage q pipeline, single barrier.
// ---------------------------------------------------------------------------
#define OM_KVS 144
#define OM_KVH 0
#define OM_Q (256 * OM_KVS + 64)          // 36928 (+64 slack for dg4 overread)
#define OM_QS 80
#define OM_QSTG 10240                     // q hi only
#define OM_NSTG 3
#define OM_DSMEM (OM_Q + OM_NSTG * OM_QSTG)   // 67648

__global__ void __launch_bounds__(256)
out_mma(const __half* __restrict__ Qph, const __half* __restrict__ KVh,
        __half* __restrict__ Yh) {
    extern __shared__ char dsm[];
    const uint32_t sb = smem_u32(dsm);
    const int tid = threadIdx.x;
    const int wid = tid >> 5, lane = tid & 31;
    const int stile = blockIdx.x, h = blockIdx.y, b = blockIdx.z;
    const int bh = b * HH + h;
    const int s0 = stile * 128;

    auto issue_q = [&](int c) {
        const uint32_t st = sb + OM_Q + (c % OM_NSTG) * OM_QSTG;
#pragma unroll
        for (int q = 0; q < 2; ++q) {
            const int idx = tid * 2 + q;
            const int r = idx >> 2, cc = idx & 3;
            const __half* ph = Qph + ((size_t)bh * SS + s0 + r) * FF + c * 32 + cc * 8;
            cp_async16(st + (uint32_t)r * OM_QS + cc * 16, ph);
        }
        asm volatile("cp.async.commit_group;" ::: "memory");
    };

    {
        const __half* ph = KVh + ((size_t)bh * FF + tid) * 72;
        const uint32_t so = sb + (uint32_t)tid * OM_KVS;
#pragma unroll
        for (int q = 0; q < 9; ++q) cp_async16(so + q * 16, ph + q * 8);
        asm volatile("cp.async.commit_group;" ::: "memory");
    }
    issue_q(0);
    issue_q(1);

    float acc[9][4];
#pragma unroll
    for (int j = 0; j < 9; ++j)
#pragma unroll
        for (int q = 0; q < 4; ++q) acc[j][q] = 0.0f;

    const int lrow = lane & 15, lch = (lane >> 4) * 16;

    for (int c = 0; c < 8; ++c) {
        if (c < 7) { asm volatile("cp.async.wait_group 1;" ::: "memory"); }
        else       { asm volatile("cp.async.wait_group 0;" ::: "memory"); }
        __syncthreads();
        if (c + 2 < 8) issue_q(c + 2);
        const uint32_t qst = sb + OM_Q + (c % OM_NSTG) * OM_QSTG;

#pragma unroll
        for (int ks = 0; ks < 2; ++ks) {
            uint32_t ah[4];
            uint32_t ad = qst + (uint32_t)(wid * 16 + lrow) * OM_QS + lch + ks * 32;
            ldm_x4(ah[0], ah[1], ah[2], ah[3], ad);
#pragma unroll
            for (int dg = 0; dg < 5; ++dg) {
                uint32_t bh4[4];
                uint32_t bd = taddr(sb + OM_KVH, OM_KVS, c * 32 + ks * 16, dg * 16, lane);
                ldm_x4_t(bh4[0], bh4[1], bh4[2], bh4[3], bd);
                const int nsel = (dg == 4) ? 1 : 2;
#pragma unroll
                for (int sel = 0; sel < 2; ++sel) {
                    if (sel >= nsel) continue;
                    const int j = dg * 2 + sel;
                    mma16816(acc[j], ah[0], ah[1], ah[2], ah[3], bh4[sel], bh4[sel + 2]);
                }
            }
        }
    }

    const int r0 = wid * 16 + (lane >> 2);
    const float den0 = __shfl_sync(0xffffffffu, acc[8][0] + acc[8][1], lane & ~3);
    const float den1 = __shfl_sync(0xffffffffu, acc[8][2] + acc[8][3], lane & ~3);
    const float inv0 = 1.0f / (den0 + 1e-8f);
    const float inv1 = 1.0f / (den1 + 1e-8f);
#pragma unroll
    for (int j = 0; j < 8; ++j) {
        const int col = h * HD + j * 8 + (lane & 3) * 2;
        float o00 = acc[j][0] * inv0, o01 = acc[j][1] * inv0;
        float o10 = acc[j][2] * inv1, o11 = acc[j][3] * inv1;
        size_t off0 = ((size_t)(b * SS + s0 + r0)) * DD + col;
        size_t off1 = ((size_t)(b * SS + s0 + r0 + 8)) * DD + col;
        *(__half2*)(Yh + off0) = __halves2half2(__float2half_rn(o00), __float2half_rn(o01));
        *(__half2*)(Yh + off1) = __halves2half2(__float2half_rn(o10), __float2half_rn(o11));
    }
}

// ---------------------------------------------------------------------------
// fused prep: x->fp16 | 4 weights->fp16 | rf->fp16 | zero kv | zero ksum
// block ranges: x [0,16384) w [16384,20480) rf [20480,20736)
//               kvz [20736,21760) ksz [21760,21776)   (kv = 1M floats = 1024 blk)
// ---------------------------------------------------------------------------
__global__ void __launch_bounds__(256)
prep_kernel(const float* __restrict__ x,
            const float* __restrict__ w0, const float* __restrict__ w1,
            const float* __restrict__ w2, const float* __restrict__ w3,
            const float* __restrict__ rf,
            __half* __restrict__ xh, __half* __restrict__ wh,
            __half* __restrict__ rfh,
            float* __restrict__ kv, float* __restrict__ ksum) {
    const int blk = blockIdx.x;
    const int tid = threadIdx.x;
    if (blk < 16384) {
        int i = (blk * 256 + tid) * 4;
        float4 v = *(const float4*)(x + i);
        *(__half2*)(xh + i)     = __halves2half2(__float2half_rn(v.x), __float2half_rn(v.y));
        *(__half2*)(xh + i + 2) = __halves2half2(__float2half_rn(v.z), __float2half_rn(v.w));
    } else if (blk < 20480) {
        int b2 = blk - 16384;
        int which = b2 >> 10;
        const float* src = (which == 0) ? w0 : (which == 1) ? w1 : (which == 2) ? w2 : w3;
        __half* dst = wh + (size_t)which * DD * DD;
        int i = ((b2 & 1023) * 256 + tid) * 4;
        float4 v = *(const float4*)(src + i);
        *(__half2*)(dst + i)     = __halves2half2(__float2half_rn(v.x), __float2half_rn(v.y));
        *(__half2*)(dst + i + 2) = __halves2half2(__float2half_rn(v.z), __float2half_rn(v.w));
    } else if (blk < 20736) {
        int i = ((blk - 20480) * 256 + tid) * 4;
        float4 v = *(const float4*)(rf + i);
        *(__half2*)(rfh + i)     = __halves2half2(__float2half_rn(v.x), __float2half_rn(v.y));
        *(__half2*)(rfh + i + 2) = __halves2half2(__float2half_rn(v.z), __float2half_rn(v.w));
    } else if (blk < 21760) {
        int i = ((blk - 20736) * 256 + tid) * 4;
        *(float4*)(kv + i) = make_float4(0.f, 0.f, 0.f, 0.f);
    } else {
        int i = ((blk - 21760) * 256 + tid) * 4;
        *(float4*)(ksum + i) = make_float4(0.f, 0.f, 0.f, 0.f);
    }
}

// ---------------------------------------------------------------------------
// launch
// ---------------------------------------------------------------------------
extern "C" void kernel_launch(void* const* d_in, const int* in_sizes, int n_in,
                              void* d_out, int out_size) {
    const float* x  = (const float*)d_in[0];
    const float* Wq = (const float*)d_in[1];
    const float* bq = (const float*)d_in[2];
    const float* Wk = (const float*)d_in[3];
    const float* bk = (const float*)d_in[4];
    const float* Wv = (const float*)d_in[5];
    const float* bv = (const float*)d_in[6];
    const float* Wo = (const float*)d_in[7];
    const float* bo = (const float*)d_in[8];
    const float* rf = (const float*)d_in[9];
    float* out = (float*)d_out;

    __half *pxh, *pwh, *prfh, *pqh, *pkh, *pvh, *pyh, *pqph, *pkph, *pkvh;
    float *pkv, *pks;
    cudaGetSymbolAddress((void**)&pxh, g_xh);
    cudaGetSymbolAddress((void**)&pwh, g_wh);
    cudaGetSymbolAddress((void**)&prfh, g_rfh);
    cudaGetSymbolAddress((void**)&pqh, g_qh);
    cudaGetSymbolAddress((void**)&pkh, g_kh);
    cudaGetSymbolAddress((void**)&pvh, g_vh);
    cudaGetSymbolAddress((void**)&pyh, g_yh);
    cudaGetSymbolAddress((void**)&pqph, g_qph);
    cudaGetSymbolAddress((void**)&pkph, g_kph);
    cudaGetSymbolAddress((void**)&pkvh, g_kvh);
    cudaGetSymbolAddress((void**)&pkv, g_kv);
    cudaGetSymbolAddress((void**)&pks, g_ksum);

    cudaFuncSetAttribute(gemm_qkv, cudaFuncAttributeMaxDynamicSharedMemorySize, GEMM_DSMEM);
    cudaFuncSetAttribute(gemm_mma_f32, cudaFuncAttributeMaxDynamicSharedMemorySize, GEMM_DSMEM);
    cudaFuncSetAttribute(phi_mma, cudaFuncAttributeMaxDynamicSharedMemorySize, PH_DSMEM);
    cudaFuncSetAttribute(kv_mma, cudaFuncAttributeMaxDynamicSharedMemorySize, KV_DSMEM);
    cudaFuncSetAttribute(out_mma, cudaFuncAttributeMaxDynamicSharedMemorySize, OM_DSMEM);

    const int WSZ = DD * DD;

    prep_kernel<<<21776, 256>>>(x, Wq, Wk, Wv, Wo, rf, pxh, pwh, prfh, pkv, pks);

    // fused Q/K/V projections
    gemm_qkv<<<dim3(DD / 128, NN / 128, 3), 256, GEMM_DSMEM>>>(
        pxh, pwh, bq, bk, bv, pqh, pkh, pvh);

    // fused q'/k' feature maps (identical bodies -> no reg-pressure union)
    phi_mma<<<dim3(SS / 128, 2, 128), 256, PH_DSMEM>>>(
        pqh, pkh, prfh, pqph, pkph);

    kv_mma<<<dim3(8, HH, BB), 256, KV_DSMEM>>>(pkph, pvh, pkv, pks);

    split_kvx<<<(BB * HH * FF + 255) / 256, 256>>>(pkv, pks, pkvh);

    out_mma<<<dim3(SS / 128, HH, BB), 256, OM_DSMEM>>>(pqph, pkvh, pyh);

    gemm_mma_f32<<<dim3(DD / 128, NN / 128), 256, GEMM_DSMEM>>>(
        pyh, pwh + 3 * WSZ, bo, out, DD);
}